// round 2
// baseline (speedup 1.0000x reference)
#include <cuda_runtime.h>
#include <cuda_bf16.h>

// Shapes (fixed): B=8, C=128, H=W=64, HW=4096, HWp=1024 (pooled), C8=16, C2=64.
#define Bb 8
#define Cc 128
#define HW 4096
#define HWP 1024
#define C8 16
#define C2 64

// Scratch (device globals; no allocation allowed)
__device__ float theta_g[Bb * C8 * HW];        // [b][c8][i]
__device__ float conv_g [Bb * 80 * HW];        // [b][cc(0..15=phi,16..79=g)][pix] pre-pool
__device__ float phi_g  [Bb * C8 * HWP];       // [b][c8][j]
__device__ float gsc_g  [Bb * HWP * C2];       // [b][j][c2]  (c2-contiguous for f32x2)

// ---------- packed f32x2 helpers ----------
__device__ __forceinline__ unsigned long long pk2(float a, float b) {
    unsigned long long r;
    asm("mov.b64 %0, {%1, %2};" : "=l"(r) : "f"(a), "f"(b));
    return r;
}
__device__ __forceinline__ unsigned long long fma2(unsigned long long a, unsigned long long b, unsigned long long c) {
    unsigned long long r;
    asm("fma.rn.f32x2 %0, %1, %2, %3;" : "=l"(r) : "l"(a), "l"(b), "l"(c));
    return r;
}
__device__ __forceinline__ unsigned long long mul2(unsigned long long a, unsigned long long b) {
    unsigned long long r;
    asm("mul.rn.f32x2 %0, %1, %2;" : "=l"(r) : "l"(a), "l"(b));
    return r;
}
__device__ __forceinline__ float2 upk2(unsigned long long a) {
    float2 r;
    asm("mov.b64 {%0, %1}, %2;" : "=f"(r.x), "=f"(r.y) : "l"(a));
    return r;
}

// ---------- Kernel 1: all 1x1 conv projections (theta full-res, phi/g full-res pre-pool) ----------
// grid (128, 6), block 256. gy=0: theta -> theta_g; gy=1: phi -> conv_g[0..15];
// gy=2..5: g rows (gy-2)*16.. -> conv_g[16+...]
__global__ void __launch_bounds__(256) proj_kernel(
    const float* __restrict__ x,
    const float* __restrict__ w_theta,
    const float* __restrict__ w_phi,
    const float* __restrict__ w_g)
{
    __shared__ __align__(16) float ws[C8 * Cc];   // 16x128
    int gy = blockIdx.y;
    const float* w;
    if (gy == 0)      w = w_theta;
    else if (gy == 1) w = w_phi;
    else              w = w_g + (gy - 2) * C8 * Cc;
    for (int idx = threadIdx.x; idx < C8 * Cc; idx += 256) ws[idx] = w[idx];
    __syncthreads();

    int t   = blockIdx.x * 256 + threadIdx.x;   // 0..32767
    int b   = t >> 12;
    int pix = t & (HW - 1);
    const float* xb = x + (size_t)b * Cc * HW + pix;

    unsigned long long acc[C8];
#pragma unroll
    for (int k = 0; k < C8; k++) acc[k] = 0ULL;

#pragma unroll 4
    for (int c = 0; c < Cc; c += 2) {
        float x0 = xb[(size_t)c * HW];
        float x1 = xb[(size_t)(c + 1) * HW];
        unsigned long long x2 = pk2(x0, x1);
#pragma unroll
        for (int k = 0; k < C8; k++) {
            const unsigned long long w2 = *(const unsigned long long*)&ws[k * Cc + c];
            acc[k] = fma2(w2, x2, acc[k]);
        }
    }

    float* dst;
    if (gy == 0) dst = theta_g + ((size_t)b * C8) * HW + pix;
    else         dst = conv_g  + ((size_t)b * 80 + (gy - 1) * 16) * HW + pix;
#pragma unroll
    for (int k = 0; k < C8; k++) {
        float2 v = upk2(acc[k]);
        dst[(size_t)k * HW] = v.x + v.y;
    }
}

// ---------- Kernel 2: 2x2 maxpool on phi/g pre-pool tensors ----------
// 8*80*1024 = 655360 outputs; grid 2560 x 256
__global__ void __launch_bounds__(256) pool_kernel()
{
    int t = blockIdx.x * 256 + threadIdx.x;
    int b   = t / (80 * HWP);
    int rem = t - b * (80 * HWP);
    int cc  = rem >> 10;
    int j   = rem & (HWP - 1);
    int py = j >> 5, px = j & 31;
    const float* src = conv_g + ((size_t)b * 80 + cc) * HW + py * 128 + px * 2;
    float m = fmaxf(fmaxf(src[0], src[1]), fmaxf(src[64], src[65]));
    if (cc < C8) phi_g[((size_t)b * C8 + cc) * HWP + j] = m;
    else         gsc_g[((size_t)b * HWP + j) * C2 + (cc - C8)] = m;
}

// ---------- Kernel 3: fused attention + output conv + residual ----------
// grid (16, 8), block 256, dyn smem 80KB.
// One thread per query index i. j streamed in 4 chunks of 256 through smem.
// No max-subtraction in softmax: |score| <~ 30 -> exp safely in fp32 range.
__global__ void __launch_bounds__(256, 2) attn_kernel(
    const float* __restrict__ x,
    const float* __restrict__ w_o,
    const float* __restrict__ gamma_p,
    float* __restrict__ out)
{
    extern __shared__ __align__(16) float sm[];
    float* phi_s = sm;            // [jl][16] : 4096 floats
    float* g_s   = sm + 4096;     // [jl][64] : 16384 floats (later reused for w_o)

    int b = blockIdx.y;
    int i = blockIdx.x * 256 + threadIdx.x;

    float th[C8];
#pragma unroll
    for (int k = 0; k < C8; k++) th[k] = theta_g[((size_t)b * C8 + k) * HW + i];

    unsigned long long acc[C2 / 2];
#pragma unroll
    for (int k = 0; k < C2 / 2; k++) acc[k] = 0ULL;
    float esum = 0.0f;

    for (int ch = 0; ch < 4; ch++) {
        int j0 = ch * 256;
        // load phi chunk transposed -> phi_s[jl][k]
        for (int idx = threadIdx.x; idx < C8 * 256; idx += 256) {
            int k = idx >> 8, jl = idx & 255;
            phi_s[jl * C8 + k] = phi_g[((size_t)b * C8 + k) * HWP + j0 + jl];
        }
        // load g chunk (already [j][c2]) with float4 copies
        {
            const float4* gsrc = (const float4*)(gsc_g + ((size_t)b * HWP + j0) * C2);
            float4* gdst = (float4*)g_s;
            for (int idx = threadIdx.x; idx < 256 * C2 / 4; idx += 256) gdst[idx] = gsrc[idx];
        }
        __syncthreads();

        for (int jl = 0; jl < 256; jl++) {
            const float4* pp = (const float4*)(phi_s + jl * C8);
            float4 p0 = pp[0], p1 = pp[1], p2 = pp[2], p3 = pp[3];
            // 4 parallel partial chains to shorten the dependency
            float sA = th[0] * p0.x;  sA = fmaf(th[4],  p1.x, sA);
            float sB = th[1] * p0.y;  sB = fmaf(th[5],  p1.y, sB);
            float sC = th[2] * p0.z;  sC = fmaf(th[6],  p1.z, sC);
            float sD = th[3] * p0.w;  sD = fmaf(th[7],  p1.w, sD);
            sA = fmaf(th[8],  p2.x, sA);  sA = fmaf(th[12], p3.x, sA);
            sB = fmaf(th[9],  p2.y, sB);  sB = fmaf(th[13], p3.y, sB);
            sC = fmaf(th[10], p2.z, sC);  sC = fmaf(th[14], p3.z, sC);
            sD = fmaf(th[11], p2.w, sD);  sD = fmaf(th[15], p3.w, sD);
            float s = (sA + sB) + (sC + sD);
            float e = __expf(s);
            esum += e;
            unsigned long long e2 = pk2(e, e);
            const unsigned long long* gj = (const unsigned long long*)(g_s + jl * C2);
#pragma unroll
            for (int k = 0; k < C2 / 2; k++) acc[k] = fma2(gj[k], e2, acc[k]);
        }
        __syncthreads();
    }

    float inv = 1.0f / esum;
    unsigned long long inv2 = pk2(inv, inv);
#pragma unroll
    for (int k = 0; k < C2 / 2; k++) acc[k] = mul2(acc[k], inv2);

    // load w_o [128][64] into g_s region
    for (int idx = threadIdx.x; idx < Cc * C2; idx += 256) g_s[idx] = w_o[idx];
    __syncthreads();

    float gamma = *gamma_p;
    const float* xb = x   + (size_t)b * Cc * HW + i;
    float*       ob = out + (size_t)b * Cc * HW + i;
#pragma unroll 4
    for (int co = 0; co < Cc; co++) {
        const unsigned long long* wo2 = (const unsigned long long*)(g_s + co * C2);
        unsigned long long r2 = 0ULL;
#pragma unroll
        for (int k = 0; k < C2 / 2; k++) r2 = fma2(wo2[k], acc[k], r2);
        float2 rv = upk2(r2);
        ob[(size_t)co * HW] = fmaf(gamma, rv.x + rv.y, xb[(size_t)co * HW]);
    }
}

extern "C" void kernel_launch(void* const* d_in, const int* in_sizes, int n_in,
                              void* d_out, int out_size)
{
    const float* x       = (const float*)d_in[0];
    const float* w_theta = (const float*)d_in[1];
    const float* w_phi   = (const float*)d_in[2];
    const float* w_g     = (const float*)d_in[3];
    const float* w_o     = (const float*)d_in[4];
    const float* gamma_p = (const float*)d_in[5];
    float* out = (float*)d_out;

    cudaFuncSetAttribute(attn_kernel, cudaFuncAttributeMaxDynamicSharedMemorySize, 80 * 1024);

    proj_kernel<<<dim3(128, 6), 256>>>(x, w_theta, w_phi, w_g);
    pool_kernel<<<2560, 256>>>();
    attn_kernel<<<dim3(16, 8), 256, 80 * 1024>>>(x, w_o, gamma_p, out);
}

// round 5
// speedup vs baseline: 2.3892x; 2.3892x over previous
#include <cuda_runtime.h>
#include <cuda_bf16.h>

#define Bb 8
#define Cc 128
#define HW 4096
#define HWP 1024
#define C8 16
#define C2 64

__device__ float theta_g[Bb * C8 * HW];   // [b][k][i]
__device__ float phi_g  [Bb * C8 * HWP];  // [b][k][j]
__device__ float gsc_g  [Bb * C2 * HWP];  // [b][c2][j]

// ---------------- helpers ----------------
__device__ __forceinline__ unsigned long long pk2(float a, float b) {
    unsigned long long r; asm("mov.b64 %0, {%1, %2};" : "=l"(r) : "f"(a), "f"(b)); return r;
}
__device__ __forceinline__ unsigned long long fma2(unsigned long long a, unsigned long long b, unsigned long long c) {
    unsigned long long r; asm("fma.rn.f32x2 %0, %1, %2, %3;" : "=l"(r) : "l"(a), "l"(b), "l"(c)); return r;
}
__device__ __forceinline__ float2 upk2(unsigned long long a) {
    float2 r; asm("mov.b64 {%0, %1}, %2;" : "=f"(r.x), "=f"(r.y) : "l"(a)); return r;
}
__device__ __forceinline__ unsigned cvt2bf(float hi, float lo) {   // {upper=hi, lower=lo}
    unsigned r; asm("cvt.rn.bf16x2.f32 %0, %1, %2;" : "=r"(r) : "f"(hi), "f"(lo)); return r;
}
// hi/lo split pack: hp = bf16x2(x,y) rounded; lp = bf16x2 of residuals
__device__ __forceinline__ void hilo(float x, float y, unsigned &hp, unsigned &lp) {
    float xh = __bfloat162float(__float2bfloat16(x));
    float yh = __bfloat162float(__float2bfloat16(y));
    hp = cvt2bf(y, x);
    lp = cvt2bf(y - yh, x - xh);
}
// D += A(bf16) * B(bf16), m16n8k16
__device__ __forceinline__ void mma16816(float* d, const unsigned* a, const unsigned* b) {
    asm volatile("mma.sync.aligned.m16n8k16.row.col.f32.bf16.bf16.f32 "
        "{%0,%1,%2,%3}, {%4,%5,%6,%7}, {%8,%9}, {%0,%1,%2,%3};"
        : "+f"(d[0]), "+f"(d[1]), "+f"(d[2]), "+f"(d[3])
        : "r"(a[0]), "r"(a[1]), "r"(a[2]), "r"(a[3]), "r"(b[0]), "r"(b[1]));
}

// ---------------- Kernel 1: theta projection ----------------
__global__ void __launch_bounds__(256) theta_kernel(
    const float* __restrict__ x, const float* __restrict__ w_theta)
{
    __shared__ __align__(16) float ws[C8 * Cc];
    for (int idx = threadIdx.x; idx < C8 * Cc; idx += 256) ws[idx] = w_theta[idx];
    __syncthreads();
    int t = blockIdx.x * 256 + threadIdx.x;
    int b = t >> 12, pix = t & (HW - 1);
    const float* xb = x + ((size_t)b << 19) + pix;
    unsigned long long acc[C8];
#pragma unroll
    for (int k = 0; k < C8; k++) acc[k] = 0ULL;
#pragma unroll 4
    for (int c = 0; c < Cc; c += 2) {
        unsigned long long x2 = pk2(xb[(size_t)c << 12], xb[(size_t)(c + 1) << 12]);
#pragma unroll
        for (int k = 0; k < C8; k++)
            acc[k] = fma2(*(const unsigned long long*)&ws[k * Cc + c], x2, acc[k]);
    }
#pragma unroll
    for (int k = 0; k < C8; k++) {
        float2 v = upk2(acc[k]);
        theta_g[(((size_t)b * C8 + k) << 12) + pix] = v.x + v.y;
    }
}

// ---------------- Kernel 2: phi/g projection fused with 2x2 maxpool ----------------
__global__ void __launch_bounds__(256) projpool_kernel(
    const float* __restrict__ x, const float* __restrict__ w_phi, const float* __restrict__ w_g)
{
    __shared__ __align__(16) unsigned long long w2s[C8 * Cc];
    int gy = blockIdx.y;
    const float* w = (gy == 0) ? w_phi : (w_g + (size_t)(gy - 1) * C8 * Cc);
    for (int idx = threadIdx.x; idx < C8 * Cc; idx += 256) { float f = w[idx]; w2s[idx] = pk2(f, f); }
    __syncthreads();

    int t = blockIdx.x * 256 + threadIdx.x;   // 0..8191
    int b = t >> 10, j = t & (HWP - 1);
    int py = j >> 5, px = j & 31;
    const float* xb = x + ((size_t)b << 19) + py * 128 + px * 2;

    unsigned long long a01[C8], a23[C8];
#pragma unroll
    for (int k = 0; k < C8; k++) { a01[k] = 0ULL; a23[k] = 0ULL; }
#pragma unroll 2
    for (int c = 0; c < Cc; c++) {
        const float* p = xb + ((size_t)c << 12);
        unsigned long long x01 = *(const unsigned long long*)p;
        unsigned long long x23 = *(const unsigned long long*)(p + 64);
#pragma unroll
        for (int k = 0; k < C8; k++) {
            unsigned long long w2 = w2s[k * Cc + c];
            a01[k] = fma2(w2, x01, a01[k]);
            a23[k] = fma2(w2, x23, a23[k]);
        }
    }
#pragma unroll
    for (int k = 0; k < C8; k++) {
        float2 v01 = upk2(a01[k]), v23 = upk2(a23[k]);
        float m = fmaxf(fmaxf(v01.x, v01.y), fmaxf(v23.x, v23.y));
        if (gy == 0) phi_g[(((size_t)b * C8 + k) << 10) + j] = m;
        else         gsc_g[(((size_t)b * C2 + (gy - 1) * C8 + k) << 10) + j] = m;
    }
}

// ---------------- Kernel 3: mma.sync flash attention + w_o conv + residual ----------------
// grid (32, 8), 256 threads (8 warps x 16 queries = 128 q/block). 8 chunks of 128 j.
// smem: PHI_HI [128j][36B], PHI_LO [128j][36B], G [64c2][272B]; epilogue reuses as W_HI/W_LO [128co][136B].
#define PHI_HI 0
#define PHI_LO 4608
#define G_OFF  9216
#define W_HI   0
#define W_LO   17408
#define SMEM_SZ 34816

__global__ void __launch_bounds__(256, 2) attn_kernel(
    const float* __restrict__ x, const float* __restrict__ w_o,
    const float* __restrict__ gamma_p, float* __restrict__ out)
{
    __shared__ __align__(16) char smem[SMEM_SZ];
    const int tid = threadIdx.x;
    const int w = tid >> 5, lane = tid & 31;
    const int gr = lane >> 2, tig = lane & 3;
    const int b = blockIdx.y;
    const int q0 = blockIdx.x * 128 + w * 16 + gr;   // this thread's first query row

    // ---- theta A fragments (hi/lo), K=16 ----
    unsigned ahi[4], alo[4];
    {
        const float* tb = theta_g + ((size_t)b << 16);
        int k0 = tig * 2;
        float x00 = tb[((size_t)k0 << 12) + q0],     x01 = tb[((size_t)(k0+1) << 12) + q0];
        float x10 = tb[((size_t)k0 << 12) + q0+8],   x11 = tb[((size_t)(k0+1) << 12) + q0+8];
        float x20 = tb[((size_t)(k0+8) << 12) + q0], x21 = tb[((size_t)(k0+9) << 12) + q0];
        float x30 = tb[((size_t)(k0+8) << 12) + q0+8], x31 = tb[((size_t)(k0+9) << 12) + q0+8];
        hilo(x00, x01, ahi[0], alo[0]);
        hilo(x10, x11, ahi[1], alo[1]);
        hilo(x20, x21, ahi[2], alo[2]);
        hilo(x30, x31, ahi[3], alo[3]);
    }

    float oacc[8][4];
#pragma unroll
    for (int nt = 0; nt < 8; nt++)
#pragma unroll
        for (int r = 0; r < 4; r++) oacc[nt][r] = 0.0f;
    float es0 = 0.0f, es1 = 0.0f;

    for (int ch = 0; ch < 8; ch++) {
        const int j0 = ch << 7;
        // ---- stage phi chunk -> [j][k] bf16 hi/lo ----
        {
            int jj = tid & 127, ks = (tid >> 7) << 3;
            const float* src = phi_g + (((size_t)(b * 16 + ks)) << 10) + j0 + jj;
            char* hb = smem + PHI_HI + jj * 36 + ks * 2;
            char* lb = smem + PHI_LO + jj * 36 + ks * 2;
#pragma unroll
            for (int u = 0; u < 8; u++) {
                float v = src[(size_t)u << 10];
                float vh = __bfloat162float(__float2bfloat16(v));
                *(__nv_bfloat16*)(hb + 2*u) = __float2bfloat16(v);
                *(__nv_bfloat16*)(lb + 2*u) = __float2bfloat16(v - vh);
            }
        }
        // ---- stage g chunk -> [c2][j] bf16 (hi only), row stride 272B ----
        {
            int c2 = tid >> 2, jq = (tid & 3) << 5;
            const float4* src = (const float4*)(gsc_g + (((size_t)(b * 64 + c2)) << 10) + j0 + jq);
            char* dst = smem + G_OFF + c2 * 272 + jq * 2;
#pragma unroll
            for (int u = 0; u < 8; u++) {
                float4 v = src[u];
                unsigned p0 = cvt2bf(v.y, v.x), p1 = cvt2bf(v.w, v.z);
                *(unsigned long long*)(dst + 8*u) = ((unsigned long long)p1 << 32) | p0;
            }
        }
        __syncthreads();

        // ---- S tiles (hi/lo x hi/lo, drop lo*lo) + exp + pack P ----
        unsigned pp[16][2];
#pragma unroll
        for (int t = 0; t < 16; t++) {
            int jl = (t << 3) + gr;
            const char* ph = smem + PHI_HI + jl * 36 + tig * 4;
            const char* pl = smem + PHI_LO + jl * 36 + tig * 4;
            unsigned bh[2] = { *(const unsigned*)ph, *(const unsigned*)(ph + 16) };
            unsigned bl[2] = { *(const unsigned*)pl, *(const unsigned*)(pl + 16) };
            float d[4] = {0.f, 0.f, 0.f, 0.f};
            mma16816(d, ahi, bh);
            mma16816(d, ahi, bl);
            mma16816(d, alo, bh);
            float e0 = __expf(d[0]), e1 = __expf(d[1]), e2 = __expf(d[2]), e3 = __expf(d[3]);
            es0 += e0 + e1; es1 += e2 + e3;
            pp[t][0] = cvt2bf(e1, e0);
            pp[t][1] = cvt2bf(e3, e2);
        }
        // ---- O += P @ g^T ----
#pragma unroll
        for (int kk = 0; kk < 8; kk++) {
            unsigned a[4] = { pp[2*kk][0], pp[2*kk][1], pp[2*kk+1][0], pp[2*kk+1][1] };
#pragma unroll
            for (int nt = 0; nt < 8; nt++) {
                int c2 = (nt << 3) + gr;
                const char* gp = smem + G_OFF + c2 * 272 + (kk * 16 + tig * 2) * 2;
                unsigned bb[2] = { *(const unsigned*)gp, *(const unsigned*)(gp + 16) };
                mma16816(oacc[nt], a, bb);
            }
        }
        __syncthreads();
    }

    // ---- softmax normalization ----
    es0 += __shfl_xor_sync(0xFFFFFFFFu, es0, 1);
    es0 += __shfl_xor_sync(0xFFFFFFFFu, es0, 2);
    es1 += __shfl_xor_sync(0xFFFFFFFFu, es1, 1);
    es1 += __shfl_xor_sync(0xFFFFFFFFu, es1, 2);
    float i0 = 1.0f / es0, i1 = 1.0f / es1;
#pragma unroll
    for (int nt = 0; nt < 8; nt++) {
        oacc[nt][0] *= i0; oacc[nt][1] *= i0;
        oacc[nt][2] *= i1; oacc[nt][3] *= i1;
    }

    // ---- stage w_o -> [co][c2] bf16 hi/lo, row stride 136B ----
    {
        int co = tid >> 1, c2h = (tid & 1) << 5;
        const float4* src = (const float4*)(w_o + co * 64 + c2h);
        char* dh = smem + W_HI + co * 136 + c2h * 2;
        char* dl = smem + W_LO + co * 136 + c2h * 2;
#pragma unroll
        for (int u = 0; u < 8; u++) {
            float4 v = src[u];
            float hx = __bfloat162float(__float2bfloat16(v.x));
            float hy = __bfloat162float(__float2bfloat16(v.y));
            float hz = __bfloat162float(__float2bfloat16(v.z));
            float hw = __bfloat162float(__float2bfloat16(v.w));
            unsigned h0 = cvt2bf(v.y, v.x), h1 = cvt2bf(v.w, v.z);
            unsigned l0 = cvt2bf(v.y - hy, v.x - hx), l1 = cvt2bf(v.w - hw, v.z - hz);
            *(unsigned long long*)(dh + 8*u) = ((unsigned long long)h1 << 32) | h0;
            *(unsigned long long*)(dl + 8*u) = ((unsigned long long)l1 << 32) | l0;
        }
    }
    __syncthreads();

    // ---- out = gamma * (o @ w_o^T) + x, via mma (A = o bf16, B = w hi/lo) ----
    const float gamma = *gamma_p;
    const float* xb = x   + ((size_t)b << 19);
    float*       ob = out + ((size_t)b << 19);

    // A fragments from normalized O (bf16 hi)
    unsigned oa[4][4];
#pragma unroll
    for (int kk = 0; kk < 4; kk++) {
        oa[kk][0] = cvt2bf(oacc[2*kk][1],   oacc[2*kk][0]);
        oa[kk][1] = cvt2bf(oacc[2*kk][3],   oacc[2*kk][2]);
        oa[kk][2] = cvt2bf(oacc[2*kk+1][1], oacc[2*kk+1][0]);
        oa[kk][3] = cvt2bf(oacc[2*kk+1][3], oacc[2*kk+1][2]);
    }

#pragma unroll
    for (int h = 0; h < 2; h++) {
        float dd[8][4];
#pragma unroll
        for (int nt = 0; nt < 8; nt++)
#pragma unroll
            for (int r = 0; r < 4; r++) dd[nt][r] = 0.0f;
#pragma unroll
        for (int kk = 0; kk < 4; kk++) {
#pragma unroll
            for (int nt = 0; nt < 8; nt++) {
                int co = ((h << 3) + nt) * 8 + gr;
                const char* wh = smem + W_HI + co * 136 + kk * 32 + tig * 4;
                const char* wl = smem + W_LO + co * 136 + kk * 32 + tig * 4;
                unsigned b0[2] = { *(const unsigned*)wh, *(const unsigned*)(wh + 16) };
                unsigned b1[2] = { *(const unsigned*)wl, *(const unsigned*)(wl + 16) };
                mma16816(dd[nt], oa[kk], b0);
                mma16816(dd[nt], oa[kk], b1);
            }
        }
#pragma unroll
        for (int nt = 0; nt < 8; nt++) {
            int co0 = (((h << 3) + nt) * 8 + tig * 2);
            size_t i00 = ((size_t)co0 << 12) + q0;
            size_t i01 = ((size_t)(co0 + 1) << 12) + q0;
            ob[i00]     = fmaf(gamma, dd[nt][0], xb[i00]);
            ob[i01]     = fmaf(gamma, dd[nt][1], xb[i01]);
            ob[i00 + 8] = fmaf(gamma, dd[nt][2], xb[i00 + 8]);
            ob[i01 + 8] = fmaf(gamma, dd[nt][3], xb[i01 + 8]);
        }
    }
}

extern "C" void kernel_launch(void* const* d_in, const int* in_sizes, int n_in,
                              void* d_out, int out_size)
{
    const float* x       = (const float*)d_in[0];
    const float* w_theta = (const float*)d_in[1];
    const float* w_phi   = (const float*)d_in[2];
    const float* w_g     = (const float*)d_in[3];
    const float* w_o     = (const float*)d_in[4];
    const float* gamma_p = (const float*)d_in[5];
    float* out = (float*)d_out;

    theta_kernel<<<128, 256>>>(x, w_theta);
    projpool_kernel<<<dim3(32, 5), 256>>>(x, w_phi, w_g);
    attn_kernel<<<dim3(32, 8), 256>>>(x, w_o, gamma_p, out);
}